// round 9
// baseline (speedup 1.0000x reference)
#include <cuda_runtime.h>
#include <cuda_bf16.h>

#define D_TOTAL   8388608
#define TABLE_N   1024
#define NBLOCKS   1184   /* 8 x 148 effective SMs — empirically best */
#define NTHREADS  256
#define SUBS      4      /* sub-iterations per chunk: 128 float4 = 2KB bursts */

__device__ float g_partials[NBLOCKS];
__device__ unsigned int g_counter = 0;

__global__ __launch_bounds__(NTHREADS) void phasecell_main(
    const int* __restrict__ ctx_phase,
    const int* __restrict__ ctx_mag,
    const int* __restrict__ self_phase,
    const int* __restrict__ self_mag,
    const float* __restrict__ cos_table,
    const float* __restrict__ exp_table,
    const float* __restrict__ cos_grad_table,
    const float* __restrict__ exp_grad_table,
    float* __restrict__ out)
{
    __shared__ float2 phase_tab[TABLE_N];  // (cos, dcos)
    __shared__ float2 mag_tab[TABLE_N];    // (exp, dexp)
    __shared__ float red[NTHREADS / 32];

    const int tid  = threadIdx.x;
    const int lane = tid & 31;
    for (int i = tid; i < TABLE_N; i += NTHREADS) {
        phase_tab[i] = make_float2(cos_table[i], cos_grad_table[i]);
        mag_tab[i]   = make_float2(exp_table[i], exp_grad_table[i]);
    }
    __syncthreads();

    const int4* cp4 = (const int4*)ctx_phase;
    const int4* sp4 = (const int4*)self_phase;
    const int4* cm4 = (const int4*)ctx_mag;
    const int4* sm4 = (const int4*)self_mag;

    float* __restrict__ out_phase = out;
    float* __restrict__ out_mag   = out + (size_t)D_TOTAL;
    float* __restrict__ out_sig   = out + (size_t)2 * D_TOTAL;
    // grad streams start at odd float offset (3D+1)/(4D+1); aligned-shifted
    // store scheme below. These bases are 16B-aligned.
    float* __restrict__ gp_base = out + (size_t)3 * D_TOTAL;
    float* __restrict__ gm_base = out + (size_t)4 * D_TOTAL;

    // Warp-chunked: chunk = 32*SUBS consecutive float4 vectors (2KB per
    // stream per warp). nvec = 2^21 = 128 * 16384 exactly.
    const int nchunks = (D_TOTAL / 4) / (32 * SUBS);             // 16384
    const int nwarps  = gridDim.x * (NTHREADS / 32);             // 9472
    const int wglobal = (blockIdx.x * NTHREADS + tid) >> 5;

    float acc = 0.0f;

    for (int ch = wglobal; ch < nchunks; ch += nwarps) {
        const int vbase = ch * (32 * SUBS) + lane;

        // ---- all loads grouped by stream: 4 x 512B = 2KB read bursts ----
        int4 A[SUBS], B[SUBS], C[SUBS], Dd[SUBS];
        #pragma unroll
        for (int j = 0; j < SUBS; j++) A[j]  = __ldcs(&cp4[vbase + 32 * j]);
        #pragma unroll
        for (int j = 0; j < SUBS; j++) B[j]  = __ldcs(&sp4[vbase + 32 * j]);
        #pragma unroll
        for (int j = 0; j < SUBS; j++) C[j]  = __ldcs(&cm4[vbase + 32 * j]);
        #pragma unroll
        for (int j = 0; j < SUBS; j++) Dd[j] = __ldcs(&sm4[vbase + 32 * j]);

        int p[SUBS][4], m[SUBS][4];
        #pragma unroll
        for (int j = 0; j < SUBS; j++) {
            p[j][0] = (A[j].x + B[j].x) & (TABLE_N - 1);
            p[j][1] = (A[j].y + B[j].y) & (TABLE_N - 1);
            p[j][2] = (A[j].z + B[j].z) & (TABLE_N - 1);
            p[j][3] = (A[j].w + B[j].w) & (TABLE_N - 1);
            m[j][0] = (C[j].x + Dd[j].x) & (TABLE_N - 1);
            m[j][1] = (C[j].y + Dd[j].y) & (TABLE_N - 1);
            m[j][2] = (C[j].z + Dd[j].z) & (TABLE_N - 1);
            m[j][3] = (C[j].w + Dd[j].w) & (TABLE_N - 1);
        }

        float  sig[SUBS][4];
        float4 gp4[SUBS], gm4[SUBS];

        #pragma unroll
        for (int j = 0; j < SUBS; j++) {
            float2 P0 = phase_tab[p[j][0]], P1 = phase_tab[p[j][1]];
            float2 P2 = phase_tab[p[j][2]], P3 = phase_tab[p[j][3]];
            float2 M0 = mag_tab[m[j][0]],   M1 = mag_tab[m[j][1]];
            float2 M2 = mag_tab[m[j][2]],   M3 = mag_tab[m[j][3]];

            sig[j][0] = P0.x * M0.x; sig[j][1] = P1.x * M1.x;
            sig[j][2] = P2.x * M2.x; sig[j][3] = P3.x * M3.x;
            acc += (sig[j][0] + sig[j][1]) + (sig[j][2] + sig[j][3]);

            float g0 = P0.y * M0.x, g1 = P1.y * M1.x;
            float g2 = P2.y * M2.x, g3 = P3.y * M3.x;
            float h0 = P0.x * M0.y, h1 = P1.x * M1.y;
            float h2 = P2.x * M2.y, h3 = P3.x * M3.y;

            // shifted window: lane i's float4 covers grad elems [4v+3..4v+6]
            float n0 = __shfl_down_sync(0xFFFFFFFFu, g0, 1);
            float n1 = __shfl_down_sync(0xFFFFFFFFu, g1, 1);
            float n2 = __shfl_down_sync(0xFFFFFFFFu, g2, 1);
            float o0 = __shfl_down_sync(0xFFFFFFFFu, h0, 1);
            float o1 = __shfl_down_sync(0xFFFFFFFFu, h1, 1);
            float o2 = __shfl_down_sync(0xFFFFFFFFu, h2, 1);
            gp4[j] = make_float4(g3, n0, n1, n2);
            gm4[j] = make_float4(h3, o0, o1, o2);

            const int vj = vbase + 32 * j;
            if (lane == 31) {               // boundary patch (no float4 slot)
                gp_base[4 * vj + 4] = g3;
                gm_base[4 * vj + 4] = h3;
            }
            if (lane == 0) {                // warp-leading 3 elements
                gp_base[4 * vj + 1] = g0;
                *(float2*)&gp_base[4 * vj + 2] = make_float2(g1, g2);
                gm_base[4 * vj + 1] = h0;
                *(float2*)&gm_base[4 * vj + 2] = make_float2(h1, h2);
            }
        }

        // ---- stores grouped per stream: 4 x 512B = 2KB write bursts ----
        #pragma unroll
        for (int j = 0; j < SUBS; j++)
            __stcs((float4*)out_phase + vbase + 32 * j,
                   make_float4((float)p[j][0], (float)p[j][1], (float)p[j][2], (float)p[j][3]));
        #pragma unroll
        for (int j = 0; j < SUBS; j++)
            __stcs((float4*)out_mag + vbase + 32 * j,
                   make_float4((float)m[j][0], (float)m[j][1], (float)m[j][2], (float)m[j][3]));
        #pragma unroll
        for (int j = 0; j < SUBS; j++)
            __stcs((float4*)out_sig + vbase + 32 * j,
                   make_float4(sig[j][0], sig[j][1], sig[j][2], sig[j][3]));
        if (lane < 31) {
            #pragma unroll
            for (int j = 0; j < SUBS; j++)
                __stcs((float4*)gp_base + vbase + 32 * j + 1, gp4[j]);
            #pragma unroll
            for (int j = 0; j < SUBS; j++)
                __stcs((float4*)gm_base + vbase + 32 * j + 1, gm4[j]);
        }
    }

#if __CUDA_ARCH__ >= 900
    cudaTriggerProgrammaticLaunchCompletion();
#endif

    // Deterministic block reduction
    #pragma unroll
    for (int off = 16; off > 0; off >>= 1)
        acc += __shfl_down_sync(0xFFFFFFFFu, acc, off);
    if (lane == 0) red[tid >> 5] = acc;
    __syncthreads();
    if (tid == 0) {
        float s = 0.0f;
        #pragma unroll
        for (int w = 0; w < NTHREADS / 32; w++) s += red[w];
        g_partials[blockIdx.x] = s;
        __threadfence();                       // release partial
        atomicAdd(&g_counter, 1u);             // signal completion
    }
}

__global__ __launch_bounds__(1024) void phasecell_reduce(float* __restrict__ out)
{
    __shared__ float red[32];
    const int tid = threadIdx.x;

    // Data-level handshake: wait until all primary blocks released partials.
    if (tid == 0) {
        while (atomicAdd(&g_counter, 0u) < (unsigned)NBLOCKS) {
#if __CUDA_ARCH__ >= 700
            __nanosleep(64);
#endif
        }
        __threadfence();                       // acquire
    }
    __syncthreads();

    // 1184 partials = 296 float4 vectors: single load round (L2).
    float a = 0.0f;
    if (tid < NBLOCKS / 4) {
        const float* p = &g_partials[tid * 4];
        float x = __ldcg(&p[0]);
        float y = __ldcg(&p[1]);
        float z = __ldcg(&p[2]);
        float w = __ldcg(&p[3]);
        a = (x + y) + (z + w);
    }
    #pragma unroll
    for (int off = 16; off > 0; off >>= 1)
        a += __shfl_down_sync(0xFFFFFFFFu, a, off);
    if ((tid & 31) == 0) red[tid >> 5] = a;
    __syncthreads();
    if (tid == 0) {
        float s = 0.0f;
        #pragma unroll
        for (int w = 0; w < 32; w++) s += red[w];
        out[(size_t)3 * D_TOTAL] = s;  // strength scalar
        g_counter = 0;                 // reset for next graph replay
    }
}

extern "C" void kernel_launch(void* const* d_in, const int* in_sizes, int n_in,
                              void* d_out, int out_size)
{
    const int*   ctx_phase  = (const int*)d_in[0];
    const int*   ctx_mag    = (const int*)d_in[1];
    const int*   self_phase = (const int*)d_in[2];
    const int*   self_mag   = (const int*)d_in[3];
    const float* cos_t      = (const float*)d_in[4];
    const float* exp_t      = (const float*)d_in[5];
    const float* cos_g      = (const float*)d_in[6];
    const float* exp_g      = (const float*)d_in[7];
    float* out = (float*)d_out;

    phasecell_main<<<NBLOCKS, NTHREADS>>>(ctx_phase, ctx_mag, self_phase, self_mag,
                                          cos_t, exp_t, cos_g, exp_g, out);

    cudaLaunchConfig_t cfg = {};
    cfg.gridDim  = dim3(1, 1, 1);
    cfg.blockDim = dim3(1024, 1, 1);
    cfg.dynamicSmemBytes = 0;
    cfg.stream = 0;

    cudaLaunchAttribute attrs[1];
    attrs[0].id = cudaLaunchAttributeProgrammaticStreamSerialization;
    attrs[0].val.programmaticStreamSerializationAllowed = 1;
    cfg.attrs = attrs;
    cfg.numAttrs = 1;

    cudaError_t e = cudaLaunchKernelEx(&cfg, phasecell_reduce, out);
    if (e != cudaSuccess) {
        phasecell_reduce<<<1, 1024>>>(out);
    }
}